// round 13
// baseline (speedup 1.0000x reference)
#include <cuda_runtime.h>
#include <cuda_fp16.h>
#include <math.h>

#define BB 32
#define LL 2048
#define DD 512
#define DFF 256
#define NBLK 6
#define EPSN 1e-6f
#define NCH 32            // score-stat chunks per batch (64 rows each)
#define LSPLIT 32         // attnv L-splits (64 rows each)
#define SCALE 0.04419417382415922f  // 1/sqrt(512)

// -------- device scratch (no allocations allowed) --------
__device__ __half2 g_kh2[(size_t)BB * LL * DD / 2];   // 64 MB fp16 k
__device__ __half2 g_vh2[(size_t)BB * LL * DD / 2];   // 64 MB fp16 v
__device__ __half g_W1h[NBLK * DD * DFF];             // fp16 W1
__device__ __half g_W2h[NBLK * DFF * DD];             // fp16 W2
__device__ float g_scores[BB * LL];
__device__ float g_m[BB][NCH];
__device__ float g_z[BB][NCH];
__device__ float g_wc[NBLK][BB * LL];                 // contiguous weights planes
__device__ float g_Apart[LSPLIT][BB][DD];             // deterministic partials
__device__ float g_q[BB * DD];                        // running q state

__device__ __forceinline__ unsigned int pack2(float a, float b) {
    __half2 h = __floats2half2_rn(a, b);
    return *reinterpret_cast<unsigned int*>(&h);
}

__device__ __forceinline__ float dot8h(uint4 u, float4 qa, float4 qb) {
    __half2 h0 = *(__half2*)&u.x, h1 = *(__half2*)&u.y;
    __half2 h2 = *(__half2*)&u.z, h3 = *(__half2*)&u.w;
    float2 f0 = __half22float2(h0), f1 = __half22float2(h1);
    float2 f2 = __half22float2(h2), f3 = __half22float2(h3);
    return f0.x * qa.x + f0.y * qa.y + f1.x * qa.z + f1.y * qa.w +
           f2.x * qb.x + f2.y * qb.y + f3.x * qb.z + f3.y * qb.w;
}

__device__ __forceinline__ void fma8h(float* acc, uint4 u, float s) {
    __half2 h0 = *(__half2*)&u.x, h1 = *(__half2*)&u.y;
    __half2 h2 = *(__half2*)&u.z, h3 = *(__half2*)&u.w;
    float2 f0 = __half22float2(h0), f1 = __half22float2(h1);
    float2 f2 = __half22float2(h2), f3 = __half22float2(h3);
    acc[0] += s * f0.x; acc[1] += s * f0.y; acc[2] += s * f1.x; acc[3] += s * f1.y;
    acc[4] += s * f2.x; acc[5] += s * f2.y; acc[6] += s * f3.x; acc[7] += s * f3.y;
}

// -------- K0 (once): convert W1,W2 to fp16 --------
__global__ void k_wconv(const float* __restrict__ W1, const float* __restrict__ W2) {
    const int idx = blockIdx.x * 256 + threadIdx.x;   // uint4 output index
    const float4* src = (const float4*)((blockIdx.y == 0) ? W1 : W2) + (size_t)idx * 2;
    const float4 f0 = src[0], f1 = src[1];
    uint4 p;
    p.x = pack2(f0.x, f0.y); p.y = pack2(f0.z, f0.w);
    p.z = pack2(f1.x, f1.y); p.w = pack2(f1.z, f1.w);
    if (blockIdx.y == 0) ((uint4*)g_W1h)[idx] = p;
    else                 ((uint4*)g_W2h)[idx] = p;
}

// -------- K1: scores + per-chunk stats; blk0 also converts k fp32->fp16 --------
// grid (NCH, BB), block 256: 8 warps x 8 rows; blk>0 loads all 16 uint4 up front
__global__ void __launch_bounds__(256, 1) k_scores(const float* __restrict__ kin,
                                                   const float* __restrict__ qin, int blk) {
    const int b = blockIdx.y, tid = threadIdx.x;
    const int w = tid >> 5, lane = tid & 31;
    const int chunk = blockIdx.x;
    const int row0 = chunk * 64 + w * 8;

    const float* qsrc = (blk == 0) ? (qin + b * DD) : (g_q + b * DD);
    const float4* q4 = (const float4*)qsrc;
    const float4 qa = q4[2 * lane],        qb = q4[2 * lane + 1];
    const float4 qc = q4[2 * (lane + 32)], qd = q4[2 * (lane + 32) + 1];

    __shared__ float sc[64];
    float sres[8];

    if (blk == 0) {
#pragma unroll
        for (int r = 0; r < 8; r++) {
            const int row = row0 + r;
            const float4* kr = (const float4*)(kin + ((size_t)b * LL + row) * DD);
            float4 a0 = kr[2 * lane], a1 = kr[2 * lane + 1];
            float4 a2 = kr[2 * lane + 64], a3 = kr[2 * lane + 65];
            uint4* kw = (uint4*)((__half*)g_kh2 + ((size_t)b * LL + row) * DD);
            uint4 p0, p1;
            p0.x = pack2(a0.x, a0.y); p0.y = pack2(a0.z, a0.w);
            p0.z = pack2(a1.x, a1.y); p0.w = pack2(a1.z, a1.w);
            p1.x = pack2(a2.x, a2.y); p1.y = pack2(a2.z, a2.w);
            p1.z = pack2(a3.x, a3.y); p1.w = pack2(a3.z, a3.w);
            kw[lane] = p0; kw[lane + 32] = p1;
            float s = a0.x * qa.x + a0.y * qa.y + a0.z * qa.z + a0.w * qa.w
                    + a1.x * qb.x + a1.y * qb.y + a1.z * qb.z + a1.w * qb.w
                    + a2.x * qc.x + a2.y * qc.y + a2.z * qc.z + a2.w * qc.w
                    + a3.x * qd.x + a3.y * qd.y + a3.z * qd.z + a3.w * qd.w;
#pragma unroll
            for (int o = 16; o > 0; o >>= 1) s += __shfl_xor_sync(0xffffffffu, s, o);
            sres[r] = s;
        }
    } else {
        const __half* kb = (const __half*)g_kh2 + ((size_t)b * LL + row0) * DD;
        uint4 r[16];
#pragma unroll
        for (int rr = 0; rr < 8; rr++) {
            const __half* kr = kb + (size_t)rr * DD;
            r[rr * 2]     = ((const uint4*)kr)[lane];
            r[rr * 2 + 1] = ((const uint4*)kr)[lane + 32];
        }
#pragma unroll
        for (int rr = 0; rr < 8; rr++) {
            float s = dot8h(r[rr * 2], qa, qb) + dot8h(r[rr * 2 + 1], qc, qd);
#pragma unroll
            for (int o = 16; o > 0; o >>= 1) s += __shfl_xor_sync(0xffffffffu, s, o);
            sres[rr] = s;
        }
    }
    if (lane == 0) {
#pragma unroll
        for (int r = 0; r < 8; r++) {
            const float v = sres[r] * SCALE;
            g_scores[b * LL + row0 + r] = v;
            sc[w * 8 + r] = v;
        }
    }
    __syncthreads();

    if (tid < 32) {
        const float a = sc[tid], c = sc[tid + 32];
        float m = fmaxf(a, c);
#pragma unroll
        for (int o = 16; o > 0; o >>= 1) m = fmaxf(m, __shfl_xor_sync(0xffffffffu, m, o));
        float e = __expf(a - m) + __expf(c - m);
#pragma unroll
        for (int o = 16; o > 0; o >>= 1) e += __shfl_xor_sync(0xffffffffu, e, o);
        if (tid == 0) { g_m[b][chunk] = m; g_z[b][chunk] = e; }
    }
}

// -------- K2: softmax finalize + contiguous weights + A partials; blk0 converts v --------
// grid (LSPLIT, BB), block 256; thread owns 8 d's, 4-way row split; blk>0 loads 16 uint4 up front
__global__ void __launch_bounds__(256, 1) k_attnv(const float* __restrict__ vin, int blk) {
    const int part = blockIdx.x, b = blockIdx.y;
    const int tid = threadIdx.x;
    __shared__ float se[64];
    __shared__ float s_m, s_inv;
    __shared__ float sacc[4][DD];

    if (tid < 32) {
        const float mc = g_m[b][tid];
        const float zc = g_z[b][tid];
        float m = mc;
#pragma unroll
        for (int o = 16; o > 0; o >>= 1) m = fmaxf(m, __shfl_xor_sync(0xffffffffu, m, o));
        float z = zc * __expf(mc - m);
#pragma unroll
        for (int o = 16; o > 0; o >>= 1) z += __shfl_xor_sync(0xffffffffu, z, o);
        if (tid == 0) { s_m = m; s_inv = 1.f / z; }
    }
    __syncthreads();
    if (tid < 64) {
        const int l = part * 64 + tid;
        const float e = __expf(g_scores[b * LL + l] - s_m) * s_inv;
        se[tid] = e;
        g_wc[blk][b * LL + l] = e;          // contiguous; transposed at the end
    }
    __syncthreads();

    const int dl = tid & 63;
    const int rg = tid >> 6;
    float acc[8] = {0.f, 0.f, 0.f, 0.f, 0.f, 0.f, 0.f, 0.f};

    if (blk == 0) {
#pragma unroll
        for (int l = rg; l < 64; l += 4) {
            const float4* vr = (const float4*)(vin + ((size_t)b * LL + part * 64 + l) * DD);
            float4 c0 = vr[2 * dl], c1 = vr[2 * dl + 1];
            uint4 p;
            p.x = pack2(c0.x, c0.y); p.y = pack2(c0.z, c0.w);
            p.z = pack2(c1.x, c1.y); p.w = pack2(c1.z, c1.w);
            ((uint4*)((__half*)g_vh2 + ((size_t)b * LL + part * 64 + l) * DD))[dl] = p;
            const float e = se[l];
            acc[0] += e * c0.x; acc[1] += e * c0.y; acc[2] += e * c0.z; acc[3] += e * c0.w;
            acc[4] += e * c1.x; acc[5] += e * c1.y; acc[6] += e * c1.z; acc[7] += e * c1.w;
        }
    } else {
        const __half* vb = (const __half*)g_vh2 + ((size_t)b * LL + part * 64) * DD;
        uint4 r[16];
#pragma unroll
        for (int i = 0; i < 16; i++)
            r[i] = ((const uint4*)(vb + (size_t)(rg + i * 4) * DD))[dl];
#pragma unroll
        for (int i = 0; i < 16; i++)
            fma8h(acc, r[i], se[rg + i * 4]);
    }
#pragma unroll
    for (int c = 0; c < 8; c++) sacc[rg][dl * 8 + c] = acc[c];
    __syncthreads();
#pragma unroll
    for (int rep = 0; rep < 2; rep++) {
        const int d = tid + rep * 256;
        g_Apart[part][b][d] = sacc[0][d] + sacc[1][d] + sacc[2][d] + sacc[3][d];
    }
}

// -------- shuffle block reduce over 512 threads --------
__device__ __forceinline__ float block_sum512(float val, float* red, int tid) {
#pragma unroll
    for (int o = 16; o > 0; o >>= 1) val += __shfl_xor_sync(0xffffffffu, val, o);
    if ((tid & 31) == 0) red[tid >> 5] = val;
    __syncthreads();
    if (tid < 32) {
        float v = (tid < 16) ? red[tid] : 0.f;
#pragma unroll
        for (int o = 8; o > 0; o >>= 1) v += __shfl_xor_sync(0xffffffffu, v, o);
        if (tid == 0) red[0] = v;
    }
    __syncthreads();
    const float r = red[0];
    __syncthreads();
    return r;
}

// -------- K3: whole FFN block per batch, 512 threads, wave-batched loads --------
// grid BB, block 512; launch_bounds(512,1) -> up to 128 regs/thread for MLP
__global__ void __launch_bounds__(512, 1) k_ffn(
        const float* __restrict__ b1, const float* __restrict__ b2,
        const float* __restrict__ a1, const float* __restrict__ bi1,
        const float* __restrict__ a2, const float* __restrict__ bi2,
        const float* __restrict__ qin, float* __restrict__ out, int blk) {
    const int b = blockIdx.x;
    const int tid = threadIdx.x;
    __shared__ float4 px[4][128];    // Apart partial quarters (8 KB)
    __shared__ float qn_s[DD];
    __shared__ float h_s[DFF];
    __shared__ float hp[16][DFF];    // W1 partials (16 KB)
    __shared__ float fp[8][DD];      // W2 partials (16 KB)
    __shared__ float y_s[DD];
    __shared__ float red[32];

    // ---- Phase A: Apart reduce ----
    {
        const int f4 = tid & 127, ps = tid >> 7;
        float4 x = make_float4(0.f, 0.f, 0.f, 0.f);
#pragma unroll
        for (int p = ps * 8; p < ps * 8 + 8; p++) {
            const float4 v = ((const float4*)g_Apart[p][b])[f4];
            x.x += v.x; x.y += v.y; x.z += v.z; x.w += v.w;
        }
        px[ps][f4] = x;
    }
    __syncthreads();

    // ---- norm1 (ddof=1) ----
    float4 x = make_float4(0.f, 0.f, 0.f, 0.f);
    if (tid < 128) {
        const float4 r0 = px[0][tid], r1 = px[1][tid], r2 = px[2][tid], r3 = px[3][tid];
        const float4* res = (const float4*)((blk == 0) ? (qin + b * DD) : (g_q + b * DD));
        const float4 rr = res[tid];
        x.x = r0.x + r1.x + r2.x + r3.x + rr.x;
        x.y = r0.y + r1.y + r2.y + r3.y + rr.y;
        x.z = r0.z + r1.z + r2.z + r3.z + rr.z;
        x.w = r0.w + r1.w + r2.w + r3.w + rr.w;
    }
    const float mu1 = block_sum512((tid < 128) ? (x.x + x.y + x.z + x.w) : 0.f, red, tid) * (1.f / DD);
    float ssq = 0.f;
    float4 t = make_float4(0.f, 0.f, 0.f, 0.f);
    if (tid < 128) {
        t.x = x.x - mu1; t.y = x.y - mu1; t.z = x.z - mu1; t.w = x.w - mu1;
        ssq = t.x * t.x + t.y * t.y + t.z * t.z + t.w * t.w;
    }
    const float var1 = block_sum512(ssq, red, tid) * (1.f / (DD - 1));
    const float inv1 = 1.f / (sqrtf(var1) + EPSN);
    if (tid < 128) {
        const float4 av = ((const float4*)(a1 + blk * DD))[tid];
        const float4 bv = ((const float4*)(bi1 + blk * DD))[tid];
        float4 qv;
        qv.x = av.x * t.x * inv1 + bv.x; qv.y = av.y * t.y * inv1 + bv.y;
        qv.z = av.z * t.z * inv1 + bv.z; qv.w = av.w * t.w * inv1 + bv.w;
        ((float4*)qn_s)[tid] = qv;
    }
    __syncthreads();

    // ---- Phase B: W1h GEMM. thread (j8 = tid&31, ds = tid>>5): 32 uint4 in 4 waves of 8 ----
    {
        const int j8 = tid & 31, ds = tid >> 5;       // 16 d-splits x 32 j-groups(8)
        const uint4* __restrict__ w1 = (const uint4*)(g_W1h + (size_t)blk * DD * DFF) + j8;
        const int d0 = ds * 32;
        float acc[8] = {0.f, 0.f, 0.f, 0.f, 0.f, 0.f, 0.f, 0.f};
#pragma unroll
        for (int wv = 0; wv < 4; wv++) {
            uint4 r[8];
#pragma unroll
            for (int i = 0; i < 8; i++)
                r[i] = w1[(size_t)(d0 + wv * 8 + i) * (DFF / 8)];
#pragma unroll
            for (int i = 0; i < 8; i++)
                fma8h(acc, r[i], qn_s[d0 + wv * 8 + i]);
        }
        float4* dst = (float4*)&hp[ds][j8 * 8];
        dst[0] = make_float4(acc[0], acc[1], acc[2], acc[3]);
        dst[1] = make_float4(acc[4], acc[5], acc[6], acc[7]);
    }
    __syncthreads();
    if (tid < DFF) {
        float s = b1[blk * DFF + tid];
#pragma unroll
        for (int ds = 0; ds < 16; ds++) s += hp[ds][tid];
        h_s[tid] = fmaxf(s, 0.f);
    }
    __syncthreads();

    // ---- Phase C: W2h GEMM. thread (d8 = tid&63, js = tid>>6): 32 uint4 in 4 waves of 8 ----
    {
        const int d8 = tid & 63, js = tid >> 6;       // 8 j-splits x 64 d-groups(8)
        const uint4* __restrict__ w2 = (const uint4*)(g_W2h + (size_t)blk * DFF * DD) + d8;
        const int j0 = js * 32;
        float acc[8] = {0.f, 0.f, 0.f, 0.f, 0.f, 0.f, 0.f, 0.f};
#pragma unroll
        for (int wv = 0; wv < 4; wv++) {
            uint4 r[8];
#pragma unroll
            for (int i = 0; i < 8; i++)
                r[i] = w2[(size_t)(j0 + wv * 8 + i) * (DD / 8)];
#pragma unroll
            for (int i = 0; i < 8; i++)
                fma8h(acc, r[i], h_s[j0 + wv * 8 + i]);
        }
        float4* dst = (float4*)&fp[js][d8 * 8];
        dst[0] = make_float4(acc[0], acc[1], acc[2], acc[3]);
        dst[1] = make_float4(acc[4], acc[5], acc[6], acc[7]);
    }
    __syncthreads();
    if (tid < 128) {
        const float4 qv = ((const float4*)qn_s)[tid];
        const float4 bv = ((const float4*)(b2 + blk * DD))[tid];
        float4 y = make_float4(qv.x + bv.x, qv.y + bv.y, qv.z + bv.z, qv.w + bv.w);
#pragma unroll
        for (int js = 0; js < 8; js++) {
            const float4 f = ((const float4*)&fp[js][0])[tid];
            y.x += f.x; y.y += f.y; y.z += f.z; y.w += f.w;
        }
        ((float4*)y_s)[tid] = y;
    }
    __syncthreads();

    // ---- Phase D: norm2 + q update + out ----
    const float y = y_s[tid];
    const float mu2 = block_sum512(y, red, tid) * (1.f / DD);
    const float t2 = y - mu2;
    const float var2 = block_sum512(t2 * t2, red, tid) * (1.f / (DD - 1));
    const float inv2 = 1.f / (sqrtf(var2) + EPSN);
    const float r = a2[blk * DD + tid] * t2 * inv2 + bi2[blk * DD + tid];
    g_q[b * DD + tid] = r;
    if (blk == 2) out[(size_t)b * 1024 + tid] = r;
    if (blk == 5) out[(size_t)b * 1024 + 512 + tid] = r;
}

// -------- K4 (once): transpose weight planes into (B,L,6) output --------
__global__ void k_wout(float* __restrict__ out_w) {
    const int idx = blockIdx.x * 256 + threadIdx.x;   // (b,l) flat
    float v[6];
#pragma unroll
    for (int c = 0; c < NBLK; c++) v[c] = g_wc[c][idx];
    float2* dst = (float2*)(out_w + (size_t)idx * NBLK);
    dst[0] = make_float2(v[0], v[1]);
    dst[1] = make_float2(v[2], v[3]);
    dst[2] = make_float2(v[4], v[5]);
}

extern "C" void kernel_launch(void* const* d_in, const int* in_sizes, int n_in,
                              void* d_out, int out_size) {
    const float* q   = (const float*)d_in[0];
    const float* k   = (const float*)d_in[1];
    const float* v   = (const float*)d_in[2];
    const float* W1  = (const float*)d_in[3];
    const float* b1  = (const float*)d_in[4];
    const float* W2  = (const float*)d_in[5];
    const float* b2  = (const float*)d_in[6];
    const float* a1  = (const float*)d_in[7];
    const float* bi1 = (const float*)d_in[8];
    const float* a2  = (const float*)d_in[9];
    const float* bi2 = (const float*)d_in[10];

    float* out   = (float*)d_out;                 // (32, 1024)
    float* out_w = (float*)d_out + BB * 2 * DD;   // (32, 2048, 6)

    k_wconv<<<dim3(NBLK * DD * DFF / 8 / 256, 2), 256>>>(W1, W2);
    for (int blk = 0; blk < NBLK; blk++) {
        k_scores<<<dim3(NCH, BB), 256>>>(k, q, blk);
        k_attnv<<<dim3(LSPLIT, BB), 256>>>(v, blk);
        k_ffn<<<BB, 512>>>(b1, b2, a1, bi1, a2, bi2, q, out, blk);
    }
    k_wout<<<BB * LL / 256, 256>>>(out_w);
}

// round 15
// speedup vs baseline: 1.1807x; 1.1807x over previous
#include <cuda_runtime.h>
#include <cuda_fp16.h>
#include <math.h>

#define BB 32
#define LL 2048
#define DD 512
#define DFF 256
#define NBLK 6
#define EPSN 1e-6f
#define NCH 32            // score-stat chunks per batch (64 rows each)
#define LSPLIT 32         // attnv L-splits (64 rows each)
#define SCALE 0.04419417382415922f  // 1/sqrt(512)

// -------- device scratch (no allocations allowed) --------
__device__ __half2 g_kh2[(size_t)BB * LL * DD / 2];   // 64 MB fp16 k
__device__ __half2 g_vh2[(size_t)BB * LL * DD / 2];   // 64 MB fp16 v
__device__ __half g_W1h[NBLK * DD * DFF];             // fp16 W1
__device__ __half g_W2h[NBLK * DFF * DD];             // fp16 W2
__device__ float g_scores[BB * LL];
__device__ float g_m[BB][NCH];
__device__ float g_z[BB][NCH];
__device__ float g_wc[NBLK][BB * LL];                 // contiguous weights planes
__device__ float g_Apart[LSPLIT][BB][DD];             // deterministic partials
__device__ float g_q[BB * DD];                        // running q state

__device__ __forceinline__ unsigned int pack2(float a, float b) {
    __half2 h = __floats2half2_rn(a, b);
    return *reinterpret_cast<unsigned int*>(&h);
}

__device__ __forceinline__ float dot8h(uint4 u, float4 qa, float4 qb) {
    __half2 h0 = *(__half2*)&u.x, h1 = *(__half2*)&u.y;
    __half2 h2 = *(__half2*)&u.z, h3 = *(__half2*)&u.w;
    float2 f0 = __half22float2(h0), f1 = __half22float2(h1);
    float2 f2 = __half22float2(h2), f3 = __half22float2(h3);
    return f0.x * qa.x + f0.y * qa.y + f1.x * qa.z + f1.y * qa.w +
           f2.x * qb.x + f2.y * qb.y + f3.x * qb.z + f3.y * qb.w;
}

__device__ __forceinline__ void fma8h(float* acc, uint4 u, float s) {
    __half2 h0 = *(__half2*)&u.x, h1 = *(__half2*)&u.y;
    __half2 h2 = *(__half2*)&u.z, h3 = *(__half2*)&u.w;
    float2 f0 = __half22float2(h0), f1 = __half22float2(h1);
    float2 f2 = __half22float2(h2), f3 = __half22float2(h3);
    acc[0] += s * f0.x; acc[1] += s * f0.y; acc[2] += s * f1.x; acc[3] += s * f1.y;
    acc[4] += s * f2.x; acc[5] += s * f2.y; acc[6] += s * f3.x; acc[7] += s * f3.y;
}

__device__ __forceinline__ void hfma8(__half2 acc[4], uint4 u, __half2 s) {
    acc[0] = __hfma2(*(__half2*)&u.x, s, acc[0]);
    acc[1] = __hfma2(*(__half2*)&u.y, s, acc[1]);
    acc[2] = __hfma2(*(__half2*)&u.z, s, acc[2]);
    acc[3] = __hfma2(*(__half2*)&u.w, s, acc[3]);
}

// -------- K0 (once): convert W1,W2 to fp16 --------
__global__ void k_wconv(const float* __restrict__ W1, const float* __restrict__ W2) {
    const int idx = blockIdx.x * 256 + threadIdx.x;   // uint4 output index
    const float4* src = (const float4*)((blockIdx.y == 0) ? W1 : W2) + (size_t)idx * 2;
    const float4 f0 = src[0], f1 = src[1];
    uint4 p;
    p.x = pack2(f0.x, f0.y); p.y = pack2(f0.z, f0.w);
    p.z = pack2(f1.x, f1.y); p.w = pack2(f1.z, f1.w);
    if (blockIdx.y == 0) ((uint4*)g_W1h)[idx] = p;
    else                 ((uint4*)g_W2h)[idx] = p;
}

// -------- K1: scores + per-chunk stats; blk0 also converts k fp32->fp16 --------
// grid (NCH, BB), block 256: 8 warps x 8 rows; blk>0 path software-pipelined
__global__ void __launch_bounds__(256) k_scores(const float* __restrict__ kin,
                                                const float* __restrict__ qin, int blk) {
    const int b = blockIdx.y, tid = threadIdx.x;
    const int w = tid >> 5, lane = tid & 31;
    const int chunk = blockIdx.x;
    const int row0 = chunk * 64 + w * 8;

    const float* qsrc = (blk == 0) ? (qin + b * DD) : (g_q + b * DD);
    const float4* q4 = (const float4*)qsrc;
    const float4 qa = q4[2 * lane],        qb = q4[2 * lane + 1];
    const float4 qc = q4[2 * (lane + 32)], qd = q4[2 * (lane + 32) + 1];

    __shared__ float sc[64];
    float sres[8];

    if (blk == 0) {
#pragma unroll
        for (int r = 0; r < 8; r++) {
            const int row = row0 + r;
            const float4* kr = (const float4*)(kin + ((size_t)b * LL + row) * DD);
            float4 a0 = kr[2 * lane], a1 = kr[2 * lane + 1];
            float4 a2 = kr[2 * lane + 64], a3 = kr[2 * lane + 65];
            uint4* kw = (uint4*)((__half*)g_kh2 + ((size_t)b * LL + row) * DD);
            uint4 p0, p1;
            p0.x = pack2(a0.x, a0.y); p0.y = pack2(a0.z, a0.w);
            p0.z = pack2(a1.x, a1.y); p0.w = pack2(a1.z, a1.w);
            p1.x = pack2(a2.x, a2.y); p1.y = pack2(a2.z, a2.w);
            p1.z = pack2(a3.x, a3.y); p1.w = pack2(a3.z, a3.w);
            kw[lane] = p0; kw[lane + 32] = p1;
            float s = a0.x * qa.x + a0.y * qa.y + a0.z * qa.z + a0.w * qa.w
                    + a1.x * qb.x + a1.y * qb.y + a1.z * qb.z + a1.w * qb.w
                    + a2.x * qc.x + a2.y * qc.y + a2.z * qc.z + a2.w * qc.w
                    + a3.x * qd.x + a3.y * qd.y + a3.z * qd.z + a3.w * qd.w;
#pragma unroll
            for (int o = 16; o > 0; o >>= 1) s += __shfl_xor_sync(0xffffffffu, s, o);
            sres[r] = s;
        }
    } else {
        const __half* kb = (const __half*)g_kh2 + ((size_t)b * LL + row0) * DD;
        uint4 A0 = ((const uint4*)kb)[lane];
        uint4 A1 = ((const uint4*)kb)[lane + 32];
        uint4 A2 = ((const uint4*)(kb + DD))[lane];
        uint4 A3 = ((const uint4*)(kb + DD))[lane + 32];
#pragma unroll
        for (int i = 0; i < 4; i++) {
            uint4 B0, B1, B2, B3;
            if (i < 3) {
                const __half* kn = kb + (size_t)(2 * i + 2) * DD;
                B0 = ((const uint4*)kn)[lane];
                B1 = ((const uint4*)kn)[lane + 32];
                B2 = ((const uint4*)(kn + DD))[lane];
                B3 = ((const uint4*)(kn + DD))[lane + 32];
            }
            float s0 = dot8h(A0, qa, qb) + dot8h(A1, qc, qd);
            float s1 = dot8h(A2, qa, qb) + dot8h(A3, qc, qd);
#pragma unroll
            for (int o = 16; o > 0; o >>= 1) {
                s0 += __shfl_xor_sync(0xffffffffu, s0, o);
                s1 += __shfl_xor_sync(0xffffffffu, s1, o);
            }
            sres[2 * i] = s0; sres[2 * i + 1] = s1;
            if (i < 3) { A0 = B0; A1 = B1; A2 = B2; A3 = B3; }
        }
    }
    if (lane == 0) {
#pragma unroll
        for (int r = 0; r < 8; r++) {
            const float v = sres[r] * SCALE;
            g_scores[b * LL + row0 + r] = v;
            sc[w * 8 + r] = v;
        }
    }
    __syncthreads();

    if (tid < 32) {
        const float a = sc[tid], c = sc[tid + 32];
        float m = fmaxf(a, c);
#pragma unroll
        for (int o = 16; o > 0; o >>= 1) m = fmaxf(m, __shfl_xor_sync(0xffffffffu, m, o));
        float e = __expf(a - m) + __expf(c - m);
#pragma unroll
        for (int o = 16; o > 0; o >>= 1) e += __shfl_xor_sync(0xffffffffu, e, o);
        if (tid == 0) { g_m[b][chunk] = m; g_z[b][chunk] = e; }
    }
}

// -------- K2: softmax finalize + contiguous weights + A partials; blk0 converts v --------
// grid (LSPLIT, BB), block 256; thread owns 8 d's, 4-way row split
__global__ void k_attnv(const float* __restrict__ vin, int blk) {
    const int part = blockIdx.x, b = blockIdx.y;
    const int tid = threadIdx.x;
    __shared__ float se[64];
    __shared__ float s_m, s_inv;
    __shared__ float sacc[4][DD];

    if (tid < 32) {
        const float mc = g_m[b][tid];
        const float zc = g_z[b][tid];
        float m = mc;
#pragma unroll
        for (int o = 16; o > 0; o >>= 1) m = fmaxf(m, __shfl_xor_sync(0xffffffffu, m, o));
        float z = zc * __expf(mc - m);
#pragma unroll
        for (int o = 16; o > 0; o >>= 1) z += __shfl_xor_sync(0xffffffffu, z, o);
        if (tid == 0) { s_m = m; s_inv = 1.f / z; }
    }
    __syncthreads();
    if (tid < 64) {
        const int l = part * 64 + tid;
        const float e = __expf(g_scores[b * LL + l] - s_m) * s_inv;
        se[tid] = e;
        g_wc[blk][b * LL + l] = e;          // contiguous; transposed at the end
    }
    __syncthreads();

    const int dl = tid & 63;
    const int rg = tid >> 6;
    float acc[8] = {0.f, 0.f, 0.f, 0.f, 0.f, 0.f, 0.f, 0.f};

    if (blk == 0) {
#pragma unroll
        for (int l = rg; l < 64; l += 4) {
            const float4* vr = (const float4*)(vin + ((size_t)b * LL + part * 64 + l) * DD);
            float4 c0 = vr[2 * dl], c1 = vr[2 * dl + 1];
            uint4 p;
            p.x = pack2(c0.x, c0.y); p.y = pack2(c0.z, c0.w);
            p.z = pack2(c1.x, c1.y); p.w = pack2(c1.z, c1.w);
            ((uint4*)((__half*)g_vh2 + ((size_t)b * LL + part * 64 + l) * DD))[dl] = p;
            const float e = se[l];
            acc[0] += e * c0.x; acc[1] += e * c0.y; acc[2] += e * c0.z; acc[3] += e * c0.w;
            acc[4] += e * c1.x; acc[5] += e * c1.y; acc[6] += e * c1.z; acc[7] += e * c1.w;
        }
    } else {
        const __half* vb = (const __half*)g_vh2 + ((size_t)b * LL + part * 64) * DD;
#pragma unroll
        for (int l = rg; l < 64; l += 4) {
            uint4 u = ((const uint4*)(vb + (size_t)l * DD))[dl];
            fma8h(acc, u, se[l]);
        }
    }
#pragma unroll
    for (int c = 0; c < 8; c++) sacc[rg][dl * 8 + c] = acc[c];
    __syncthreads();
#pragma unroll
    for (int rep = 0; rep < 2; rep++) {
        const int d = tid + rep * 256;
        g_Apart[part][b][d] = sacc[0][d] + sacc[1][d] + sacc[2][d] + sacc[3][d];
    }
}

// -------- shuffle block reduce over 512 threads --------
__device__ __forceinline__ float block_sum512(float val, float* red, int tid) {
#pragma unroll
    for (int o = 16; o > 0; o >>= 1) val += __shfl_xor_sync(0xffffffffu, val, o);
    if ((tid & 31) == 0) red[tid >> 5] = val;
    __syncthreads();
    if (tid < 32) {
        float v = (tid < 16) ? red[tid] : 0.f;
#pragma unroll
        for (int o = 8; o > 0; o >>= 1) v += __shfl_xor_sync(0xffffffffu, v, o);
        if (tid == 0) red[0] = v;
    }
    __syncthreads();
    const float r = red[0];
    __syncthreads();
    return r;
}

// -------- K3: whole FFN block per batch, 512 threads, wave-batched + hfma2 --------
// grid BB, block 512; launch_bounds(512,1) -> up to 128 regs/thread for MLP
__global__ void __launch_bounds__(512, 1) k_ffn(
        const float* __restrict__ b1, const float* __restrict__ b2,
        const float* __restrict__ a1, const float* __restrict__ bi1,
        const float* __restrict__ a2, const float* __restrict__ bi2,
        const float* __restrict__ qin, float* __restrict__ out, int blk) {
    const int b = blockIdx.x;
    const int tid = threadIdx.x;
    __shared__ float4 px[4][128];    // Apart partial quarters (8 KB); reused as qn_h/h_h
    __shared__ float qn_s[DD];
    __shared__ float h_s[DFF];
    __shared__ float hp[16][DFF];    // W1 partials (16 KB)
    __shared__ float fp[8][DD];      // W2 partials (16 KB)
    __shared__ float y_s[DD];
    __shared__ float red[32];

    __half2* qn_h = (__half2*)px;            // 2 KB overlay (px dead after norm1)
    __half2* h_h  = ((__half2*)px) + DD;     // 1 KB overlay

    // ---- Phase A: Apart reduce ----
    {
        const int f4 = tid & 127, ps = tid >> 7;
        float4 x = make_float4(0.f, 0.f, 0.f, 0.f);
#pragma unroll
        for (int p = ps * 8; p < ps * 8 + 8; p++) {
            const float4 v = ((const float4*)g_Apart[p][b])[f4];
            x.x += v.x; x.y += v.y; x.z += v.z; x.w += v.w;
        }
        px[ps][f4] = x;
    }
    __syncthreads();

    // ---- norm1 (ddof=1) ----
    float4 x = make_float4(0.f, 0.f, 0.f, 0.f);
    if (tid < 128) {
        const float4 r0 = px[0][tid], r1 = px[1][tid], r2 = px[2][tid], r3 = px[3][tid];
        const float4* res = (const float4*)((blk == 0) ? (qin + b * DD) : (g_q + b * DD));
        const float4 rr = res[tid];
        x.x = r0.x + r1.x + r2.x + r3.x + rr.x;
        x.y = r0.y + r1.y + r2.y + r3.y + rr.y;
        x.z = r0.z + r1.z + r2.z + r3.z + rr.z;
        x.w = r0.w + r1.w + r2.w + r3.w + rr.w;
    }
    const float mu1 = block_sum512((tid < 128) ? (x.x + x.y + x.z + x.w) : 0.f, red, tid) * (1.f / DD);
    float ssq = 0.f;
    float4 t = make_float4(0.f, 0.f, 0.f, 0.f);
    if (tid < 128) {
        t.x = x.x - mu1; t.y = x.y - mu1; t.z = x.z - mu1; t.w = x.w - mu1;
        ssq = t.x * t.x + t.y * t.y + t.z * t.z + t.w * t.w;
    }
    const float var1 = block_sum512(ssq, red, tid) * (1.f / (DD - 1));
    const float inv1 = 1.f / (sqrtf(var1) + EPSN);
    if (tid < 128) {
        const float4 av = ((const float4*)(a1 + blk * DD))[tid];
        const float4 bv = ((const float4*)(bi1 + blk * DD))[tid];
        float4 qv;
        qv.x = av.x * t.x * inv1 + bv.x; qv.y = av.y * t.y * inv1 + bv.y;
        qv.z = av.z * t.z * inv1 + bv.z; qv.w = av.w * t.w * inv1 + bv.w;
        ((float4*)qn_s)[tid] = qv;
        // broadcast-half2 copy for the hfma2 GEMM (overlays px[0], already consumed)
        qn_h[4 * tid + 0] = __half2half2(__float2half_rn(qv.x));
        qn_h[4 * tid + 1] = __half2half2(__float2half_rn(qv.y));
        qn_h[4 * tid + 2] = __half2half2(__float2half_rn(qv.z));
        qn_h[4 * tid + 3] = __half2half2(__float2half_rn(qv.w));
    }
    __syncthreads();

    // ---- Phase B: W1h GEMM. thread (j8 = tid&31, ds = tid>>5): 32 uint4, 4 waves, hfma2 ----
    {
        const int j8 = tid & 31, ds = tid >> 5;       // 16 d-splits x 32 j-groups(8)
        const uint4* __restrict__ w1 = (const uint4*)(g_W1h + (size_t)blk * DD * DFF) + j8;
        const int d0 = ds * 32;
        __half2 acc2[4];
        acc2[0] = acc2[1] = acc2[2] = acc2[3] = __float2half2_rn(0.f);
#pragma unroll
        for (int wv = 0; wv < 4; wv++) {
            uint4 r[8];
#pragma unroll
            for (int i = 0; i < 8; i++)
                r[i] = w1[(size_t)(d0 + wv * 8 + i) * (DFF / 8)];
#pragma unroll
            for (int i = 0; i < 8; i++)
                hfma8(acc2, r[i], qn_h[d0 + wv * 8 + i]);
        }
        const float2 f0 = __half22float2(acc2[0]), f1 = __half22float2(acc2[1]);
        const float2 f2 = __half22float2(acc2[2]), f3 = __half22float2(acc2[3]);
        float4* dst = (float4*)&hp[ds][j8 * 8];
        dst[0] = make_float4(f0.x, f0.y, f1.x, f1.y);
        dst[1] = make_float4(f2.x, f2.y, f3.x, f3.y);
    }
    __syncthreads();
    if (tid < DFF) {
        float s = b1[blk * DFF + tid];
#pragma unroll
        for (int ds = 0; ds < 16; ds++) s += hp[ds][tid];
        const float hv = fmaxf(s, 0.f);
        h_s[tid] = hv;
        h_h[tid] = __half2half2(__float2half_rn(hv));
    }
    __syncthreads();

    // ---- Phase C: W2h GEMM. thread (d8 = tid&63, js = tid>>6): 32 uint4, 4 waves, hfma2 ----
    {
        const int d8 = tid & 63, js = tid >> 6;       // 8 j-splits x 64 d-groups(8)
        const uint4* __restrict__ w2 = (const uint4*)(g_W2h + (size_t)blk * DFF * DD) + d8;
        const int j0 = js * 32;
        __half2 acc2[4];
        acc2[0] = acc2[1] = acc2[2] = acc2[3] = __float2half2_rn(0.f);
#pragma unroll
        for (int wv = 0; wv < 4; wv++) {
            uint4 r[8];
#pragma unroll
            for (int i = 0; i < 8; i++)
                r[i] = w2[(size_t)(j0 + wv * 8 + i) * (DD / 8)];
#pragma unroll
            for (int i = 0; i < 8; i++)
                hfma8(acc2, r[i], h_h[j0 + wv * 8 + i]);
        }
        const float2 f0 = __half22float2(acc2[0]), f1 = __half22float2(acc2[1]);
        const float2 f2 = __half22float2(acc2[2]), f3 = __half22float2(acc2[3]);
        float4* dst = (float4*)&fp[js][d8 * 8];
        dst[0] = make_float4(f0.x, f0.y, f1.x, f1.y);
        dst[1] = make_float4(f2.x, f2.y, f3.x, f3.y);
    }
    __syncthreads();
    if (tid < 128) {
        const float4 qv = ((const float4*)qn_s)[tid];
        const float4 bv = ((const float4*)(b2 + blk * DD))[tid];
        float4 y = make_float4(qv.x + bv.x, qv.y + bv.y, qv.z + bv.z, qv.w + bv.w);
#pragma unroll
        for (int js = 0; js < 8; js++) {
            const float4 f = ((const float4*)&fp[js][0])[tid];
            y.x += f.x; y.y += f.y; y.z += f.z; y.w += f.w;
        }
        ((float4*)y_s)[tid] = y;
    }
    __syncthreads();

    // ---- Phase D: norm2 + q update + out ----
    const float y = y_s[tid];
    const float mu2 = block_sum512(y, red, tid) * (1.f / DD);
    const float t2 = y - mu2;
    const float var2 = block_sum512(t2 * t2, red, tid) * (1.f / (DD - 1));
    const float inv2 = 1.f / (sqrtf(var2) + EPSN);
    const float r = a2[blk * DD + tid] * t2 * inv2 + bi2[blk * DD + tid];
    g_q[b * DD + tid] = r;
    if (blk == 2) out[(size_t)b * 1024 + tid] = r;
    if (blk == 5) out[(size_t)b * 1024 + 512 + tid] = r;
}

// -------- K4 (once): transpose weight planes into (B,L,6) output --------
__global__ void k_wout(float* __restrict__ out_w) {
    const int idx = blockIdx.x * 256 + threadIdx.x;   // (b,l) flat
    float v[6];
#pragma unroll
    for (int c = 0; c < NBLK; c++) v[c] = g_wc[c][idx];
    float2* dst = (float2*)(out_w + (size_t)idx * NBLK);
    dst[0] = make_float2(v[0], v[1]);
    dst[1] = make_float2(v[2], v[3]);
    dst[2] = make_float2(v[4], v[5]);
}

extern "C" void kernel_launch(void* const* d_in, const int* in_sizes, int n_in,
                              void* d_out, int out_size) {
    const float* q   = (const float*)d_in[0];
    const float* k   = (const float*)d_in[1];
    const float* v   = (const float*)d_in[2];
    const float* W1  = (const float*)d_in[3];
    const float* b1  = (const float*)d_in[4];
    const float* W2  = (const float*)d_in[5];
    const float* b2  = (const float*)d_in[6];
    const float* a1  = (const float*)d_in[7];
    const float* bi1 = (const float*)d_in[8];
    const float* a2  = (const float*)d_in[9];
    const float* bi2 = (const float*)d_in[10];

    float* out   = (float*)d_out;                 // (32, 1024)
    float* out_w = (float*)d_out + BB * 2 * DD;   // (32, 2048, 6)

    k_wconv<<<dim3(NBLK * DD * DFF / 8 / 256, 2), 256>>>(W1, W2);
    for (int blk = 0; blk < NBLK; blk++) {
        k_scores<<<dim3(NCH, BB), 256>>>(k, q, blk);
        k_attnv<<<dim3(LSPLIT, BB), 256>>>(v, blk);
        k_ffn<<<BB, 512>>>(b1, b2, a1, bi1, a2, bi2, q, out, blk);
    }
    k_wout<<<BB * LL / 256, 256>>>(out_w);
}